// round 2
// baseline (speedup 1.0000x reference)
#include <cuda_runtime.h>
#include <cstdint>
#include <math.h>

#define NCn 100000
#define NEn 150000
#define EE  600000
#define H   128
#define D   64

typedef unsigned long long ull;

// ---------------- device scratch (static, no allocations) ----------------
__device__ float g_hc[NCn * H];
__device__ float g_he[NEn * H];
__device__ float g_hs[NEn * H];     // projected-src buffer (max NE rows)
__device__ float g_mean[NEn * H];   // SAGE mean buffer
__device__ float g_c1[NCn * H];
__device__ float g_e1[NEn * H];
__device__ float g_c2[NCn * H];
__device__ float g_e2[NEn * H];
__device__ float g_c3[NCn * D];
__device__ float g_e3[NEn * D];
__device__ float g_asrc[NEn * 4];
__device__ float g_adst[NEn * 4];
__device__ float g_Avs[H * 4];
__device__ float g_Avd[H * 4];
__device__ float g_Wsum[H * H];
__device__ int   g_rowptr[6][NEn + 1];
__device__ int   g_col[6][EE];
__device__ int   g_cnt[NEn];
__device__ int   g_bsums[1024];

// ---------------- f32x2 helpers ----------------
__device__ __forceinline__ ull pack2(float x, float y) {
    ull r; asm("mov.b64 %0,{%1,%2};" : "=l"(r) : "f"(x), "f"(y)); return r;
}
__device__ __forceinline__ ull dupf(float x) {
    ull r; asm("mov.b64 %0,{%1,%1};" : "=l"(r) : "f"(x)); return r;
}
__device__ __forceinline__ ull fma2(ull a, ull b, ull c) {
    ull d; asm("fma.rn.f32x2 %0,%1,%2,%3;" : "=l"(d) : "l"(a), "l"(b), "l"(c)); return d;
}
__device__ __forceinline__ void unpack2(ull v, float& x, float& y) {
    asm("mov.b64 {%0,%1},%2;" : "=f"(x), "=f"(y) : "l"(v));
}

// ---------------- GEMM: C[N,NCOLS] (=|+=) A[N,128] * B[128,NCOLS] ----------------
template <int NCOLS>
__global__ void __launch_bounds__(256) gemm_k128(const float* __restrict__ A,
                                                 const float* __restrict__ B,
                                                 float* __restrict__ C, int N,
                                                 int accflag) {
    constexpr int TX = NCOLS / 4;   // threads along cols (32 or 16)
    constexpr int TY = 256 / TX;    // 8 or 16
    constexpr int RPT = 64 / TY;    // rows per thread: 8 or 4
    extern __shared__ unsigned char smraw[];
    float (*As)[132] = reinterpret_cast<float(*)[132]>(smraw);
    ull* Bs = reinterpret_cast<ull*>(smraw + 64 * 132 * sizeof(float));

    const int tid = threadIdx.x;
    const int row0 = blockIdx.x * 64;

    // load B [128][NCOLS] as packed col-pairs
    for (int i = tid; i < 128 * (NCOLS / 4); i += 256) {
        int k = i / (NCOLS / 4), cq = i % (NCOLS / 4);
        float4 f = __ldg(reinterpret_cast<const float4*>(B) + i);
        Bs[k * (NCOLS / 2) + cq * 2]     = pack2(f.x, f.y);
        Bs[k * (NCOLS / 2) + cq * 2 + 1] = pack2(f.z, f.w);
    }
    // load A tile [64][128]
    for (int i = tid; i < 64 * 32; i += 256) {
        int r = i >> 5, kq = i & 31;
        float4 f = make_float4(0.f, 0.f, 0.f, 0.f);
        if (row0 + r < N)
            f = __ldg(reinterpret_cast<const float4*>(A) + (size_t)(row0 + r) * 32 + kq);
        *reinterpret_cast<float4*>(&As[r][kq * 4]) = f;
    }
    __syncthreads();

    const int tx = tid % TX, ty = tid / TX;
    const int rb = ty * RPT;
    ull acc[RPT][2];
#pragma unroll
    for (int j = 0; j < RPT; j++) { acc[j][0] = 0ull; acc[j][1] = 0ull; }

#pragma unroll 4
    for (int k = 0; k < 128; k++) {
        ulonglong2 b = *reinterpret_cast<const ulonglong2*>(&Bs[k * (NCOLS / 2) + tx * 2]);
#pragma unroll
        for (int j = 0; j < RPT; j++) {
            ull a2 = dupf(As[rb + j][k]);
            acc[j][0] = fma2(a2, b.x, acc[j][0]);
            acc[j][1] = fma2(a2, b.y, acc[j][1]);
        }
    }
#pragma unroll
    for (int j = 0; j < RPT; j++) {
        int r = row0 + rb + j;
        if (r < N) {
            float4 v;
            unpack2(acc[j][0], v.x, v.y);
            unpack2(acc[j][1], v.z, v.w);
            float4* cp = reinterpret_cast<float4*>(C + (size_t)r * NCOLS) + tx;
            if (accflag) {
                float4 o = *cp;
                v.x += o.x; v.y += o.y; v.z += o.z; v.w += o.w;
            }
            *cp = v;
        }
    }
}

// ---------------- small kernels ----------------
__global__ void zero_int(int* p, int n) {
    int i = blockIdx.x * blockDim.x + threadIdx.x;
    if (i < n) p[i] = 0;
}
__global__ void hist_dst(const int* __restrict__ dst, int* cnt, int n) {
    int i = blockIdx.x * blockDim.x + threadIdx.x;
    if (i < n) atomicAdd(&cnt[dst[i]], 1);
}
__global__ void scan_block(const int* __restrict__ cnt, int* __restrict__ out,
                           int* __restrict__ bsums, int n) {
    __shared__ int sh[256];
    int tid = threadIdx.x;
    int base = blockIdx.x * 1024 + tid * 4;
    int v0 = 0, v1 = 0, v2 = 0, v3 = 0;
    if (base + 0 < n) v0 = cnt[base + 0];
    if (base + 1 < n) v1 = cnt[base + 1];
    if (base + 2 < n) v2 = cnt[base + 2];
    if (base + 3 < n) v3 = cnt[base + 3];
    int ts = v0 + v1 + v2 + v3;
    int val = ts;
    sh[tid] = val; __syncthreads();
    for (int off = 1; off < 256; off <<= 1) {
        int t = (tid >= off) ? sh[tid - off] : 0;
        __syncthreads();
        val += t; sh[tid] = val; __syncthreads();
    }
    int excl = val - ts;
    if (base + 0 < n) out[base + 0] = excl; excl += v0;
    if (base + 1 < n) out[base + 1] = excl; excl += v1;
    if (base + 2 < n) out[base + 2] = excl; excl += v2;
    if (base + 3 < n) out[base + 3] = excl;
    if (tid == 255) bsums[blockIdx.x] = val;
}
__global__ void scan_top(int* data, int n) {
    __shared__ int sh[256];
    int tid = threadIdx.x;
    int base = tid * 4;
    int v0 = 0, v1 = 0, v2 = 0, v3 = 0;
    if (base + 0 < n) v0 = data[base + 0];
    if (base + 1 < n) v1 = data[base + 1];
    if (base + 2 < n) v2 = data[base + 2];
    if (base + 3 < n) v3 = data[base + 3];
    int ts = v0 + v1 + v2 + v3;
    int val = ts;
    sh[tid] = val; __syncthreads();
    for (int off = 1; off < 256; off <<= 1) {
        int t = (tid >= off) ? sh[tid - off] : 0;
        __syncthreads();
        val += t; sh[tid] = val; __syncthreads();
    }
    int excl = val - ts;
    if (base + 0 < n) data[base + 0] = excl; excl += v0;
    if (base + 1 < n) data[base + 1] = excl; excl += v1;
    if (base + 2 < n) data[base + 2] = excl; excl += v2;
    if (base + 3 < n) data[base + 3] = excl;
}
__global__ void scan_add(int* rowptr, const int* __restrict__ bsums, int n, int total) {
    int i = blockIdx.x * blockDim.x + threadIdx.x;
    if (i < n) rowptr[i] += bsums[i >> 10];
    if (i == 0) rowptr[n] = total;
}
__global__ void fill_csr(const int* __restrict__ src, const int* __restrict__ dst,
                         const int* __restrict__ rowptr, int* pos, int* col, int n) {
    int i = blockIdx.x * blockDim.x + threadIdx.x;
    if (i < n) {
        int d = dst[i];
        int p = rowptr[d] + atomicAdd(&pos[d], 1);
        col[p] = src[i];
    }
}

__global__ void encoder(const float* __restrict__ X, const float* __restrict__ W,
                        const float* __restrict__ b, float* __restrict__ out,
                        int N, int inF) {
    int t = blockIdx.x * blockDim.x + threadIdx.x;
    int row = t >> 5, cq = t & 31;
    if (row >= N) return;
    float4 acc = __ldg(reinterpret_cast<const float4*>(b) + cq);
    for (int k = 0; k < inF; k++) {
        float xv = __ldg(&X[(size_t)row * inF + k]);
        float4 wv = __ldg(reinterpret_cast<const float4*>(W) + k * 32 + cq);
        acc.x += xv * wv.x; acc.y += xv * wv.y; acc.z += xv * wv.z; acc.w += xv * wv.w;
    }
    acc.x = fmaxf(acc.x, 0.f); acc.y = fmaxf(acc.y, 0.f);
    acc.z = fmaxf(acc.z, 0.f); acc.w = fmaxf(acc.w, 0.f);
    reinterpret_cast<float4*>(out)[(size_t)row * 32 + cq] = acc;
}

// As[k][h] = sum_j W[k][h*32+j]*a_s[h][j]; same for Ad
__global__ void compute_av(const float* __restrict__ W, const float* __restrict__ as,
                           const float* __restrict__ ad, float* As, float* Ad) {
    int t = threadIdx.x;  // 512 threads
    int k = t >> 2, h = t & 3;
    float sa = 0.f, sd = 0.f;
    for (int j = 0; j < 32; j++) {
        float w = W[k * H + h * 32 + j];
        sa += w * as[h * 32 + j];
        sd += w * ad[h * 32 + j];
    }
    As[k * 4 + h] = sa;
    Ad[k * 4 + h] = sd;
}

// out[n,4] = X[n,128] @ M[128,4]   (warp per row)
__global__ void matvec4(const float* __restrict__ X, const float* __restrict__ M,
                        float* __restrict__ out, int N) {
    int gt = blockIdx.x * blockDim.x + threadIdx.x;
    int w = gt >> 5;
    if (w >= N) return;
    int lane = threadIdx.x & 31;
    float4 x = __ldg(reinterpret_cast<const float4*>(X) + (size_t)w * 32 + lane);
    float4 p = make_float4(0.f, 0.f, 0.f, 0.f);
    int k0 = lane * 4;
#pragma unroll
    for (int i = 0; i < 4; i++) {
        float4 m = __ldg(reinterpret_cast<const float4*>(M) + (k0 + i));
        float xv = (i == 0) ? x.x : (i == 1) ? x.y : (i == 2) ? x.z : x.w;
        p.x += xv * m.x; p.y += xv * m.y; p.z += xv * m.z; p.w += xv * m.w;
    }
    for (int off = 16; off; off >>= 1) {
        p.x += __shfl_down_sync(0xffffffffu, p.x, off);
        p.y += __shfl_down_sync(0xffffffffu, p.y, off);
        p.z += __shfl_down_sync(0xffffffffu, p.z, off);
        p.w += __shfl_down_sync(0xffffffffu, p.w, off);
    }
    if (lane == 0) reinterpret_cast<float4*>(out)[w] = p;
}

// GAT aggregation: warp per dst node, in-register segment softmax (no max pass)
__global__ void gat_agg(const int* __restrict__ rowptr, const int* __restrict__ col,
                        const float* __restrict__ hs, const float* __restrict__ asrc,
                        const float* __restrict__ adst, float* __restrict__ out,
                        int nd, int accflag) {
    int w = (blockIdx.x * blockDim.x + threadIdx.x) >> 5;
    if (w >= nd) return;
    int lane = threadIdx.x & 31;
    int h = lane >> 3;
    int s0 = rowptr[w], s1 = rowptr[w + 1];
    float ad = __ldg(&adst[(size_t)w * 4 + h]);
    float den = 0.f;
    for (int e = s0; e < s1; e++) {
        int s = __ldg(&col[e]);
        float x = __ldg(&asrc[(size_t)s * 4 + h]) + ad;
        x = (x > 0.f) ? x : 0.2f * x;
        den += __expf(x);
    }
    float rden = (s1 > s0) ? 1.f / den : 0.f;
    float4 acc = make_float4(0.f, 0.f, 0.f, 0.f);
    for (int e = s0; e < s1; e++) {
        int s = __ldg(&col[e]);
        float x = __ldg(&asrc[(size_t)s * 4 + h]) + ad;
        x = (x > 0.f) ? x : 0.2f * x;
        float al = __expf(x) * rden;
        float4 hv = __ldg(reinterpret_cast<const float4*>(hs + (size_t)s * H) + lane);
        acc.x += al * hv.x; acc.y += al * hv.y; acc.z += al * hv.z; acc.w += al * hv.w;
    }
    float4* op = reinterpret_cast<float4*>(out + (size_t)w * H) + lane;
    if (accflag) {
        float4 o = *op;
        acc.x += o.x; acc.y += o.y; acc.z += o.z; acc.w += o.w;
    }
    *op = acc;
}

// SAGE mean aggregation: warp per dst node
__global__ void sage_mean(const int* __restrict__ rowptr, const int* __restrict__ col,
                          const float* __restrict__ x, float* __restrict__ out, int nd) {
    int w = (blockIdx.x * blockDim.x + threadIdx.x) >> 5;
    if (w >= nd) return;
    int lane = threadIdx.x & 31;
    int s0 = rowptr[w], s1 = rowptr[w + 1];
    float4 acc = make_float4(0.f, 0.f, 0.f, 0.f);
    for (int e = s0; e < s1; e++) {
        int s = __ldg(&col[e]);
        float4 hv = __ldg(reinterpret_cast<const float4*>(x + (size_t)s * H) + lane);
        acc.x += hv.x; acc.y += hv.y; acc.z += hv.z; acc.w += hv.w;
    }
    float sc = 1.f / fmaxf((float)(s1 - s0), 1.f);
    acc.x *= sc; acc.y *= sc; acc.z *= sc; acc.w *= sc;
    reinterpret_cast<float4*>(out + (size_t)w * H)[lane] = acc;
}

__global__ void bias_relu3(float* __restrict__ X, const float* __restrict__ b0,
                           const float* __restrict__ b1, const float* __restrict__ b2,
                           int nrows) {
    size_t i = (size_t)blockIdx.x * blockDim.x + threadIdx.x;
    if (i >= (size_t)nrows * H) return;
    int c = (int)(i & (H - 1));
    float v = X[i] + __ldg(&b0[c]) + __ldg(&b1[c]) + __ldg(&b2[c]);
    X[i] = (v > 0.f) ? v : 0.f;
}
__global__ void add3(float* o, const float* a, const float* b, const float* c, int n) {
    int i = blockIdx.x * blockDim.x + threadIdx.x;
    if (i < n) o[i] = a[i] + b[i] + c[i];
}
__global__ void add2(float* o, const float* a, const float* b, int n) {
    int i = blockIdx.x * blockDim.x + threadIdx.x;
    if (i < n) o[i] = a[i] + b[i];
}

// bias add + L2-normalize rows of [N,64] -> out
__global__ void norm_out(const float* __restrict__ X, const float* __restrict__ b0,
                         const float* __restrict__ b1, float* __restrict__ out, int N) {
    int gt = blockIdx.x * blockDim.x + threadIdx.x;
    int w = gt >> 5;
    if (w >= N) return;
    int lane = threadIdx.x & 31;
    float v0 = X[(size_t)w * 64 + lane] + __ldg(&b0[lane]) + __ldg(&b1[lane]);
    float v1 = X[(size_t)w * 64 + 32 + lane] + __ldg(&b0[32 + lane]) + __ldg(&b1[32 + lane]);
    float ss = v0 * v0 + v1 * v1;
    for (int off = 16; off; off >>= 1) ss += __shfl_xor_sync(0xffffffffu, ss, off);
    float sc = 1.f / fmaxf(sqrtf(ss), 1e-12f);
    out[(size_t)w * 64 + lane] = v0 * sc;
    out[(size_t)w * 64 + 32 + lane] = v1 * sc;
}

// ---------------- host ----------------
static inline int cdiv(int a, int b) { return (a + b - 1) / b; }

extern "C" void kernel_launch(void* const* d_in, const int* in_sizes, int n_in,
                              void* d_out, int out_size) {
    const float* xc    = (const float*)d_in[0];
    const float* xe    = (const float*)d_in[1];
    const float* Wc    = (const float*)d_in[2];
    const float* bc    = (const float*)d_in[3];
    const float* We    = (const float*)d_in[4];
    const float* be    = (const float*)d_in[5];
    const float* gatW  = (const float*)d_in[6];
    const float* gatAs = (const float*)d_in[7];
    const float* gatAd = (const float*)d_in[8];
    const float* gatB  = (const float*)d_in[9];
    const float* s2Wl  = (const float*)d_in[10];
    const float* s2bl  = (const float*)d_in[11];
    const float* s2Wr  = (const float*)d_in[12];
    const float* s3Wl  = (const float*)d_in[13];
    const float* s3bl  = (const float*)d_in[14];
    const float* s3Wr  = (const float*)d_in[15];
    float* out = (float*)d_out;

    void* p;
    cudaGetSymbolAddress(&p, g_hc);    float* hc   = (float*)p;
    cudaGetSymbolAddress(&p, g_he);    float* he   = (float*)p;
    cudaGetSymbolAddress(&p, g_hs);    float* hs   = (float*)p;
    cudaGetSymbolAddress(&p, g_mean);  float* mean = (float*)p;
    cudaGetSymbolAddress(&p, g_c1);    float* c1   = (float*)p;
    cudaGetSymbolAddress(&p, g_e1);    float* e1   = (float*)p;
    cudaGetSymbolAddress(&p, g_c2);    float* c2   = (float*)p;
    cudaGetSymbolAddress(&p, g_e2);    float* e2   = (float*)p;
    cudaGetSymbolAddress(&p, g_c3);    float* c3   = (float*)p;
    cudaGetSymbolAddress(&p, g_e3);    float* e3   = (float*)p;
    cudaGetSymbolAddress(&p, g_asrc);  float* asrc = (float*)p;
    cudaGetSymbolAddress(&p, g_adst);  float* adst = (float*)p;
    cudaGetSymbolAddress(&p, g_Avs);   float* Avs  = (float*)p;
    cudaGetSymbolAddress(&p, g_Avd);   float* Avd  = (float*)p;
    cudaGetSymbolAddress(&p, g_Wsum);  float* Wsum = (float*)p;
    cudaGetSymbolAddress(&p, g_rowptr); int* rowptr0 = (int*)p;
    cudaGetSymbolAddress(&p, g_col);    int* col0    = (int*)p;
    cudaGetSymbolAddress(&p, g_cnt);    int* cnt     = (int*)p;
    cudaGetSymbolAddress(&p, g_bsums);  int* bsums   = (int*)p;

    constexpr int SMEM128 = 64 * 132 * 4 + 128 * 64 * 8;  // 99328
    constexpr int SMEM64  = 64 * 132 * 4 + 128 * 32 * 8;  // 66560
    cudaFuncSetAttribute(gemm_k128<128>, cudaFuncAttributeMaxDynamicSharedMemorySize, SMEM128);
    cudaFuncSetAttribute(gemm_k128<64>,  cudaFuncAttributeMaxDynamicSharedMemorySize, SMEM64);

    // ---- CSR build for 6 edge types ----
    struct { const int* ei; int nd; } T[6] = {
        {(const int*)d_in[16], NCn}, {(const int*)d_in[17], NCn}, {(const int*)d_in[18], NCn},
        {(const int*)d_in[19], NEn}, {(const int*)d_in[20], NEn}, {(const int*)d_in[21], NEn}};
    for (int t = 0; t < 6; t++) {
        int nd = T[t].nd;
        const int* src = T[t].ei;
        const int* dst = src + EE;
        int* rp = rowptr0 + t * (NEn + 1);
        int* cl = col0 + (size_t)t * EE;
        zero_int<<<cdiv(nd, 256), 256>>>(cnt, nd);
        hist_dst<<<cdiv(EE, 256), 256>>>(dst, cnt, EE);
        int nb = cdiv(nd, 1024);
        scan_block<<<nb, 256>>>(cnt, rp, bsums, nd);
        scan_top<<<1, 256>>>(bsums, nb);
        scan_add<<<cdiv(nd, 256), 256>>>(rp, bsums, nd, EE);
        zero_int<<<cdiv(nd, 256), 256>>>(cnt, nd);
        fill_csr<<<cdiv(EE, 256), 256>>>(src, dst, rp, cnt, cl, EE);
    }

    // ---- encoders ----
    encoder<<<cdiv(NCn * 32, 256), 256>>>(xc, Wc, bc, hc, NCn, 5);
    encoder<<<cdiv(NEn * 32, 256), 256>>>(xe, We, be, he, NEn, 4);

    // ---- Layer 1: GAT over 6 edge types ----
    const int HH = H * H;
    for (int t = 0; t < 6; t++) {
        const float* W = gatW + (size_t)t * HH;
        compute_av<<<1, 512>>>(W, gatAs + t * 128, gatAd + t * 128, Avs, Avd);
        const float* xs; int ns; const float* xd; int nd; float* dbuf; int accf;
        if (t < 3)      { xs = he; ns = NEn; xd = hc; nd = NCn; dbuf = c1; accf = (t > 0); }
        else if (t == 3){ xs = he; ns = NEn; xd = he; nd = NEn; dbuf = e1; accf = 0; }
        else            { xs = hc; ns = NCn; xd = he; nd = NEn; dbuf = e1; accf = 1; }
        matvec4<<<cdiv(ns * 32, 256), 256>>>(xs, Avs, asrc, ns);
        matvec4<<<cdiv(nd * 32, 256), 256>>>(xd, Avd, adst, nd);
        gemm_k128<128><<<cdiv(ns, 64), 256, SMEM128>>>(xs, W, hs, ns, 0);
        int* rp = rowptr0 + t * (NEn + 1);
        int* cl = col0 + (size_t)t * EE;
        gat_agg<<<cdiv(nd * 32, 256), 256>>>(rp, cl, hs, asrc, adst, dbuf, nd, accf);
    }
    bias_relu3<<<cdiv(NCn * H, 256), 256>>>(c1, gatB, gatB + H, gatB + 2 * H, NCn);
    bias_relu3<<<cdiv(NEn * H, 256), 256>>>(e1, gatB + 3 * H, gatB + 4 * H, gatB + 5 * H, NEn);

    // ---- Layer 2: SAGE (H -> H) ----
    int* rp0 = rowptr0;                 int* cl_0 = col0;
    int* rp1 = rowptr0 + 1 * (NEn + 1); int* cl_1 = col0 + 1ul * EE;
    int* rp2 = rowptr0 + 2 * (NEn + 1); int* cl_2 = col0 + 2ul * EE;
    int* rp3 = rowptr0 + 3 * (NEn + 1); int* cl_3 = col0 + 3ul * EE;
    int* rp4 = rowptr0 + 4 * (NEn + 1); int* cl_4 = col0 + 4ul * EE;
    int* rp5 = rowptr0 + 5 * (NEn + 1); int* cl_5 = col0 + 5ul * EE;

    add3<<<cdiv(HH, 256), 256>>>(Wsum, s2Wr, s2Wr + HH, s2Wr + 2 * HH, HH);
    sage_mean<<<cdiv(NCn * 32, 256), 256>>>(rp0, cl_0, e1, mean, NCn);
    gemm_k128<128><<<cdiv(NCn, 64), 256, SMEM128>>>(mean, s2Wl, c2, NCn, 0);
    sage_mean<<<cdiv(NCn * 32, 256), 256>>>(rp1, cl_1, e1, mean, NCn);
    gemm_k128<128><<<cdiv(NCn, 64), 256, SMEM128>>>(mean, s2Wl + HH, c2, NCn, 1);
    sage_mean<<<cdiv(NCn * 32, 256), 256>>>(rp2, cl_2, e1, mean, NCn);
    gemm_k128<128><<<cdiv(NCn, 64), 256, SMEM128>>>(mean, s2Wl + 2 * HH, c2, NCn, 1);
    gemm_k128<128><<<cdiv(NCn, 64), 256, SMEM128>>>(c1, Wsum, c2, NCn, 1);
    bias_relu3<<<cdiv(NCn * H, 256), 256>>>(c2, s2bl, s2bl + H, s2bl + 2 * H, NCn);

    add3<<<cdiv(HH, 256), 256>>>(Wsum, s2Wr + 3 * HH, s2Wr + 4 * HH, s2Wr + 5 * HH, HH);
    sage_mean<<<cdiv(NEn * 32, 256), 256>>>(rp3, cl_3, e1, mean, NEn);
    gemm_k128<128><<<cdiv(NEn, 64), 256, SMEM128>>>(mean, s2Wl + 3 * HH, e2, NEn, 0);
    sage_mean<<<cdiv(NEn * 32, 256), 256>>>(rp4, cl_4, c1, mean, NEn);
    gemm_k128<128><<<cdiv(NEn, 64), 256, SMEM128>>>(mean, s2Wl + 4 * HH, e2, NEn, 1);
    sage_mean<<<cdiv(NEn * 32, 256), 256>>>(rp5, cl_5, c1, mean, NEn);
    gemm_k128<128><<<cdiv(NEn, 64), 256, SMEM128>>>(mean, s2Wl + 5 * HH, e2, NEn, 1);
    gemm_k128<128><<<cdiv(NEn, 64), 256, SMEM128>>>(e1, Wsum, e2, NEn, 1);
    bias_relu3<<<cdiv(NEn * H, 256), 256>>>(e2, s2bl + 3 * H, s2bl + 4 * H, s2bl + 5 * H, NEn);

    // ---- Layer 3: SAGE (H -> D) over 4 edge types [emp, board, codir, revemp] ----
    const int HD2 = H * D;
    add2<<<cdiv(HD2, 256), 256>>>(Wsum, s3Wr, s3Wr + HD2, HD2);
    sage_mean<<<cdiv(NCn * 32, 256), 256>>>(rp0, cl_0, e2, mean, NCn);
    gemm_k128<64><<<cdiv(NCn, 64), 256, SMEM64>>>(mean, s3Wl, c3, NCn, 0);
    sage_mean<<<cdiv(NCn * 32, 256), 256>>>(rp1, cl_1, e2, mean, NCn);
    gemm_k128<64><<<cdiv(NCn, 64), 256, SMEM64>>>(mean, s3Wl + HD2, c3, NCn, 1);
    gemm_k128<64><<<cdiv(NCn, 64), 256, SMEM64>>>(c2, Wsum, c3, NCn, 1);
    norm_out<<<cdiv(NCn * 32, 256), 256>>>(c3, s3bl, s3bl + D, out, NCn);

    add2<<<cdiv(HD2, 256), 256>>>(Wsum, s3Wr + 2 * HD2, s3Wr + 3 * HD2, HD2);
    sage_mean<<<cdiv(NEn * 32, 256), 256>>>(rp3, cl_3, e2, mean, NEn);
    gemm_k128<64><<<cdiv(NEn, 64), 256, SMEM64>>>(mean, s3Wl + 2 * HD2, e3, NEn, 0);
    sage_mean<<<cdiv(NEn * 32, 256), 256>>>(rp4, cl_4, c2, mean, NEn);
    gemm_k128<64><<<cdiv(NEn, 64), 256, SMEM64>>>(mean, s3Wl + 3 * HD2, e3, NEn, 1);
    gemm_k128<64><<<cdiv(NEn, 64), 256, SMEM64>>>(e2, Wsum, e3, NEn, 1);
    norm_out<<<cdiv(NEn * 32, 256), 256>>>(e3, s3bl + 2 * D, s3bl + 3 * D,
                                           out + (size_t)NCn * D, NEn);
}